// round 7
// baseline (speedup 1.0000x reference)
#include <cuda_runtime.h>
#include <math.h>

#define BB 16
#define Q  8400
#define CC 80
#define G  64
#define RADIUS (2.5f/32.0f)

// ---- scratch (static device globals; no runtime allocation) ----
__device__ float              g_cost[(long long)BB*G*Q];   // [b][g][q]
__device__ unsigned long long g_mask[BB*Q];                // per-anchor GT bitmask
__device__ int                g_rowarg[BB*Q];              // argmin_g cost0[q][g]

// =====================================================================
// Kernel A: warp-per-anchor cost build; label-deduped class cost.
// =====================================================================
#define TBA 512
#define QPB 16
__global__ void __launch_bounds__(TBA)
build_cost_kernel(const float* __restrict__ logits,
                  const float* __restrict__ boxes,
                  const int*   __restrict__ labels,
                  const float* __restrict__ gtboxes)
{
    int b = blockIdx.y;
    int qbase = blockIdx.x * QPB;
    int t = threadIdx.x;
    int w = t >> 5, l = t & 31;

    __shared__ float s_gx[G*4];
    __shared__ float s_cx[G], s_cy[G], s_area[G];
    __shared__ int   s_lab[G];
    __shared__ float s_cost[G][QPB+1];
    __shared__ int   s_ulab[G];
    __shared__ unsigned char s_map[G];
    __shared__ int   s_nu;
    __shared__ int   s_c2s[CC];

    if (t < G) {
        float4 gb = ((const float4*)gtboxes)[b*G + t];
        s_cx[t]=gb.x; s_cy[t]=gb.y;
        float x0=gb.x-0.5f*gb.z, y0=gb.y-0.5f*gb.w;
        float x1=gb.x+0.5f*gb.z, y1=gb.y+0.5f*gb.w;
        s_gx[t*4+0]=x0; s_gx[t*4+1]=y0; s_gx[t*4+2]=x1; s_gx[t*4+3]=y1;
        s_area[t]=(x1-x0)*(y1-y0);
        s_lab[t]=labels[b*G+t];
    }
    if (t < CC) s_c2s[t] = -1;
    __syncthreads();
    if (t == 0) {
        int nu = 0;
        for (int g=0; g<G; g++) {
            int c = s_lab[g];
            int sl = s_c2s[c];
            if (sl < 0) { sl = nu; s_c2s[c] = sl; s_ulab[nu++] = c; }
            s_map[g] = (unsigned char)sl;
        }
        s_nu = nu;
    }
    __syncthreads();

    int q = qbase + w;
    if (q < Q) {
        float4 pb = ((const float4*)boxes)[b*Q + q];
        float ax = pb.x, ay = pb.y;
        float bx0 = pb.x-0.5f*pb.z, by0 = pb.y-0.5f*pb.w;
        float bx1 = pb.x+0.5f*pb.z, by1 = pb.y+0.5f*pb.w;
        float areaA = (bx1-bx0)*(by1-by0);
        const float* lrow = logits + ((long long)b*Q + q)*CC;

        // ---- class cost for unique labels only ----
        int nu = s_nu;
        float clsv0 = 0.0f, clsv1 = 0.0f;
        #pragma unroll
        for (int h=0; h<2; h++) {
            int u = l + h*32;
            if (u < nu) {
                float x = __ldg(lrow + s_ulab[u]);
                float p = 1.0f/(1.0f + expf(-x));
                float neg = 0.75f * p*p * (-logf(1.0f - p + 1e-8f));
                float pos = 0.25f * (1.0f-p)*(1.0f-p) * (-logf(p + 1e-8f));
                float cls = pos - neg;
                if (h) clsv1 = cls; else clsv0 = cls;
            }
        }

        float costv[2];
        bool  anyflag = false;
        bool  iibcv[2];

        #pragma unroll
        for (int h=0; h<2; h++) {
            int g = l + h*32;
            bool ib = (ax>s_gx[g*4+0]) && (ax<s_gx[g*4+2]) &&
                      (ay>s_gx[g*4+1]) && (ay<s_gx[g*4+3]);
            bool ic = (ax>s_cx[g]-RADIUS)&&(ax<s_cx[g]+RADIUS)&&
                      (ay>s_cy[g]-RADIUS)&&(ay<s_cy[g]+RADIUS);
            anyflag |= (ib | ic);
            iibcv[h] = ib && ic;
        }
        unsigned ball = __ballot_sync(0xffffffffu, anyflag);
        float fgterm = ball ? 0.0f : 10000.0f;

        #pragma unroll
        for (int h=0; h<2; h++) {
            int g = l + h*32;
            int slot = s_map[g];
            float a0 = __shfl_sync(0xffffffffu, clsv0, slot & 31);
            float a1 = __shfl_sync(0xffffffffu, clsv1, slot & 31);
            float cls = (slot < 32) ? a0 : a1;

            float gx0=s_gx[g*4+0], gy0=s_gx[g*4+1], gx1=s_gx[g*4+2], gy1=s_gx[g*4+3];
            float ltx=fmaxf(bx0,gx0), lty=fmaxf(by0,gy0);
            float rbx=fminf(bx1,gx1), rby=fminf(by1,gy1);
            float iw=fmaxf(rbx-ltx,0.0f), ih=fmaxf(rby-lty,0.0f);
            float inter = iw*ih;
            float uni   = areaA + s_area[g] - inter;
            float iou   = inter/uni;
            float ex0=fminf(bx0,gx0), ey0=fminf(by0,gy0);
            float ex1=fmaxf(bx1,gx1), ey1=fmaxf(by1,gy1);
            float encl = fmaxf(ex1-ex0,0.0f)*fmaxf(ey1-ey0,0.0f);
            float giou = iou - (encl - uni)/encl;

            costv[h] = cls - 3.0f*giou + (iibcv[h] ? 0.0f : 100.0f) + fgterm;
            s_cost[g][w] = costv[h];
        }

        float bv; int bg;
        if (costv[1] < costv[0]) { bv = costv[1]; bg = l+32; }
        else                     { bv = costv[0]; bg = l;    }
        #pragma unroll
        for (int off=16; off; off>>=1) {
            float ov = __shfl_down_sync(0xffffffffu, bv, off);
            int   og = __shfl_down_sync(0xffffffffu, bg, off);
            if (ov < bv || (ov==bv && og < bg)) { bv=ov; bg=og; }
        }
        if (l==0) {
            g_rowarg[b*Q+q] = bg;
            g_mask  [b*Q+q] = 0ULL;
        }
    }
    __syncthreads();

    int r0 = t >> 4, j = t & 15;
    int qq = qbase + j;
    if (qq < Q) {
        float* p = g_cost + ((long long)b*G + r0)*Q + qq;
        #pragma unroll
        for (int r = r0; r < G; r += 32) {
            *p = s_cost[r][j];
            p += (size_t)32*Q;
        }
    }
}

// =====================================================================
// Kernel B: per (b,g) column, single pass; register-resident lists.
// =====================================================================
#define TKB 256
__global__ void __launch_bounds__(TKB)
select_kernel(const float* __restrict__ boxes,
              const float* __restrict__ gtboxes)
{
    int b = blockIdx.x >> 6, g = blockIdx.x & 63;
    const float* cost = g_cost + ((long long)b*G+g)*Q;
    const float4* abox = (const float4*)boxes + (long long)b*Q;
    int t = threadIdx.x;

    float4 gb = __ldg(&((const float4*)gtboxes)[b*G+g]);
    float gx0=gb.x-0.5f*gb.z, gy0=gb.y-0.5f*gb.w;
    float gx1=gb.x+0.5f*gb.z, gy1=gb.y+0.5f*gb.w;
    float areaG=(gx1-gx0)*(gy1-gy0);

    __shared__ float s_pv[TKB*10];
    __shared__ int   s_pi[TKB*10];
    __shared__ int   s_dynk;

    float itop[10];
    float pv[10]; int pi[10];
    #pragma unroll
    for (int i=0;i<10;i++) { itop[i]=-INFINITY; pv[i]=INFINITY; pi[i]=0x7FFFFFFF; }

    for (int q=t; q<Q; q+=TKB) {
        float4 pb = __ldg(abox + q);
        float bx0 = pb.x-0.5f*pb.z, by0 = pb.y-0.5f*pb.w;
        float bx1 = pb.x+0.5f*pb.z, by1 = pb.y+0.5f*pb.w;
        float areaA = (bx1-bx0)*(by1-by0);
        float ltx=fmaxf(bx0,gx0), lty=fmaxf(by0,gy0);
        float rbx=fminf(bx1,gx1), rby=fminf(by1,gy1);
        float iw=fmaxf(rbx-ltx,0.0f), ih=fmaxf(rby-lty,0.0f);
        float inter = iw*ih;
        float uni   = areaA + areaG - inter;
        float iou   = inter/uni;

        if (iou > itop[9]) {
            float nv = iou;
            #pragma unroll
            for (int i=0;i<10;i++) {
                float cur = itop[i];
                bool take = nv > cur;
                itop[i] = take ? nv : cur;
                nv      = take ? cur : nv;
            }
        }

        float v = cost[q];
        if (v < pv[9]) {
            float nv = v; int ni = q;
            #pragma unroll
            for (int i=0;i<10;i++) {
                float cv = pv[i]; int ci = pi[i];
                bool take = (nv < cv) || (nv == cv && ni < ci);
                pv[i] = take ? nv : cv;  pi[i] = take ? ni : ci;
                nv    = take ? cv : nv;  ni    = take ? ci : ni;
            }
        }
    }

    #pragma unroll
    for (int i=0;i<10;i++) s_pv[t*10+i] = itop[i];
    __syncthreads();
    for (int s=TKB/2; s>=1; s>>=1) {
        if (t < s) {
            float a[10], c[10], m[10];
            #pragma unroll
            for (int i=0;i<10;i++){ a[i]=s_pv[t*10+i]; c[i]=s_pv[(t+s)*10+i]; }
            int ia=0, ic=0;
            #pragma unroll
            for (int i=0;i<10;i++) m[i] = (a[ia] >= c[ic]) ? a[ia++] : c[ic++];
            #pragma unroll
            for (int i=0;i<10;i++) s_pv[t*10+i] = m[i];
        }
        __syncthreads();
    }
    if (t==0) {
        float ssum = 0.0f;
        for (int i=0;i<10;i++) ssum += s_pv[i];
        int k = (int)ssum;
        if (k < 1) k = 1;
        if (k > 10) k = 10;
        s_dynk = k;
    }
    __syncthreads();

    #pragma unroll
    for (int i=0;i<10;i++) { s_pv[t*10+i]=pv[i]; s_pi[t*10+i]=pi[i]; }
    __syncthreads();
    for (int s=TKB/2; s>=1; s>>=1) {
        if (t < s) {
            float av[10], bv[10], mv[10];
            int   ai[10], bi[10], mi[10];
            #pragma unroll
            for (int i=0;i<10;i++){
                av[i]=s_pv[t*10+i];     ai[i]=s_pi[t*10+i];
                bv[i]=s_pv[(t+s)*10+i]; bi[i]=s_pi[(t+s)*10+i];
            }
            int ia=0, ic=0;
            #pragma unroll
            for (int i=0;i<10;i++) {
                bool takeA = (av[ia] < bv[ic]) ||
                             (av[ia]==bv[ic] && ai[ia] < bi[ic]);
                if (takeA) { mv[i]=av[ia]; mi[i]=ai[ia]; ia++; }
                else       { mv[i]=bv[ic]; mi[i]=bi[ic]; ic++; }
            }
            #pragma unroll
            for (int i=0;i<10;i++){ s_pv[t*10+i]=mv[i]; s_pi[t*10+i]=mi[i]; }
        }
        __syncthreads();
    }
    if (t==0) {
        int k = s_dynk;
        for (int j=0; j<k; j++)
            atomicOr(&g_mask[b*Q + s_pi[j]], 1ULL<<g);
    }
}

// =====================================================================
// Kernel C: single-pass resolve (the while-loop provably runs <= 1 body):
//  dedup -> counts -> one round of column argmins over UNMATCHED rows
//  -> outputs with closed-form penalty (prologue-matched rows: +1e5*T).
// =====================================================================
#define TDR 1024
#define NWR (TDR/32)
#define NWORD ((Q+31)/32)
#define Q4 (Q/4)
#define SMEM_RES (Q*8 + NWORD*4 + 32)
__global__ void __launch_bounds__(TDR)
resolve_kernel(char* __restrict__ out_bytes, int layoutB)
{
    extern __shared__ char sm[];
    unsigned long long* smask = (unsigned long long*)sm;            // Q
    unsigned* bmp = (unsigned*)(sm + (size_t)Q*8);                  // NWORD (prologue-matched)

    int b = blockIdx.x, t = threadIdx.x;
    int wid = t/32, lane = t%32;
    const float* cost = g_cost + (long long)b*G*Q;
    const int*   rowarg = g_rowarg + b*Q;

    __shared__ int s_cnt[G];
    __shared__ int s_unm[G];
    __shared__ int s_addq[G];
    __shared__ int s_n;

    for (int i=t; i<NWORD; i+=TDR) bmp[i] = 0u;
    if (t < G) s_cnt[t] = 0;
    if (t == 0) s_n = 0;
    __syncthreads();

    // dedup + counts + prologue-matched bitmap
    for (int q=t; q<Q; q+=TDR) {
        unsigned long long m = g_mask[b*Q+q];
        if (__popcll(m) > 1) m = 1ULL << rowarg[q];
        smask[q] = m;
        if (m) {
            atomicOr(&bmp[q>>5], 1u << (q&31));
            unsigned long long mm = m;
            while (mm) { int g = __ffsll((long long)mm)-1; atomicAdd(&s_cnt[g],1); mm &= mm-1; }
        }
    }
    __syncthreads();
    if (t < G && s_cnt[t] == 0) s_unm[atomicAdd(&s_n,1)] = t;
    __syncthreads();
    int n_un = s_n;
    float penT = n_un > 0 ? 100000.0f : 0.0f;

    // one round of column argmins over unmatched rows (snapshot = bmp)
    for (int u = wid; u < n_un; u += NWR) {
        int g = s_unm[u];
        const float4* cg4 = (const float4*)(cost + (long long)g*Q);
        float bv = INFINITY; int bi = Q;
        #pragma unroll 4
        for (int i = lane; i < Q4; i += 32) {
            unsigned wbits = bmp[i >> 3];
            unsigned nib = (wbits >> ((i & 7)*4)) & 0xFu;
            float4 c = __ldg(cg4 + i);
            int q0 = i*4;
            if (!(nib & 1u) && c.x < bv) { bv=c.x; bi=q0;   }
            if (!(nib & 2u) && c.y < bv) { bv=c.y; bi=q0+1; }
            if (!(nib & 4u) && c.z < bv) { bv=c.z; bi=q0+2; }
            if (!(nib & 8u) && c.w < bv) { bv=c.w; bi=q0+3; }
        }
        #pragma unroll
        for (int off=16; off; off>>=1) {
            float ov = __shfl_down_sync(0xffffffffu, bv, off);
            int   oi = __shfl_down_sync(0xffffffffu, bi, off);
            if (ov < bv || (ov==bv && oi < bi)) { bv=ov; bi=oi; }
        }
        if (lane==0) s_addq[u] = bi;
    }
    __syncthreads();
    if (t < n_un && s_addq[t] < Q)
        atomicOr(&smask[s_addq[t]], 1ULL << s_unm[t]);
    __syncthreads();

    // ---- outputs ----
    if (layoutB) {
        unsigned char* out_sel = (unsigned char*)out_bytes;
        int* out_asn = (int*)(out_bytes + (size_t)BB*Q);
        int* out_mq  = (int*)(out_bytes + (size_t)BB*Q + (size_t)4*BB*Q);
        for (int q=t; q<Q; q+=TDR) {
            unsigned long long m = smask[q];
            out_sel[b*Q+q] = m ? 1 : 0;
            out_asn[b*Q+q] = m ? (__ffsll((long long)m)-1) : 0;
        }
        for (int g=wid; g<G; g+=NWR) {
            const float* cg = cost + (long long)g*Q;
            float bv = INFINITY; int bi = 0;
            for (int q=lane; q<Q; q+=32) {
                if ((smask[q]>>g) & 1ULL) {
                    float pen = ((bmp[q>>5] >> (q&31)) & 1u) ? penT : 0.0f;
                    float v = cg[q] + pen;
                    if (v < bv) { bv=v; bi=q; }
                }
            }
            #pragma unroll
            for (int off=16; off; off>>=1) {
                float ov = __shfl_down_sync(0xffffffffu, bv, off);
                int   oi = __shfl_down_sync(0xffffffffu, bi, off);
                if (ov < bv || (ov==bv && oi < bi)) { bv=ov; bi=oi; }
            }
            if (lane==0) out_mq[b*G+g] = bi;
        }
    } else {
        float* out = (float*)out_bytes;
        float* out_sel = out;
        float* out_asn = out + BB*Q;
        float* out_mq  = out + 2*BB*Q;
        for (int q=t; q<Q; q+=TDR) {
            unsigned long long m = smask[q];
            out_sel[b*Q+q] = m ? 1.0f : 0.0f;
            out_asn[b*Q+q] = m ? (float)(__ffsll((long long)m)-1) : 0.0f;
        }
        for (int g=wid; g<G; g+=NWR) {
            const float* cg = cost + (long long)g*Q;
            float bv = INFINITY; int bi = 0;
            for (int q=lane; q<Q; q+=32) {
                if ((smask[q]>>g) & 1ULL) {
                    float pen = ((bmp[q>>5] >> (q&31)) & 1u) ? penT : 0.0f;
                    float v = cg[q] + pen;
                    if (v < bv) { bv=v; bi=q; }
                }
            }
            #pragma unroll
            for (int off=16; off; off>>=1) {
                float ov = __shfl_down_sync(0xffffffffu, bv, off);
                int   oi = __shfl_down_sync(0xffffffffu, bi, off);
                if (ov < bv || (ov==bv && oi < bi)) { bv=ov; bi=oi; }
            }
            if (lane==0) out_mq[b*G+g] = (float)bi;
        }
    }
}

// =====================================================================
extern "C" void kernel_launch(void* const* d_in, const int* in_sizes, int n_in,
                              void* d_out, int out_size)
{
    const float* logits = 0; const float* boxes = 0;
    const int*   labels = 0; const float* gtb   = 0;
    for (int i = 0; i < n_in; i++) {
        switch (in_sizes[i]) {
            case BB*Q*CC: logits = (const float*)d_in[i]; break;
            case BB*Q*4:  boxes  = (const float*)d_in[i]; break;
            case BB*G:    labels = (const int*)  d_in[i]; break;
            case BB*G*4:  gtb    = (const float*)d_in[i]; break;
        }
    }

    int layoutB = (out_size == BB*Q + 4*BB*Q + 4*BB*G) ? 1 : 0;

    static int smem_set = 0;
    if (!smem_set) {
        cudaFuncSetAttribute(resolve_kernel,
                             cudaFuncAttributeMaxDynamicSharedMemorySize,
                             SMEM_RES);
        smem_set = 1;
    }

    dim3 gA((Q + QPB - 1)/QPB, BB);
    build_cost_kernel<<<gA, TBA>>>(logits, boxes, labels, gtb);
    select_kernel<<<BB*G, TKB>>>(boxes, gtb);
    resolve_kernel<<<BB, TDR, SMEM_RES>>>((char*)d_out, layoutB);
}

// round 8
// speedup vs baseline: 1.1185x; 1.1185x over previous
#include <cuda_runtime.h>
#include <math.h>

#define BB 16
#define Q  8400
#define CC 80
#define G  64
#define RADIUS (2.5f/32.0f)
#define NWORD ((Q+31)/32)
#define Q4 (Q/4)

// ---- scratch (static device globals; no runtime allocation) ----
__device__ float              g_cost[(long long)BB*G*Q];   // [b][g][q]
__device__ unsigned long long g_mask[BB*Q];                // per-anchor GT bitmask
__device__ int                g_rowarg[BB*Q];              // argmin_g cost0[q][g]
__device__ int                g_ulab[BB*G];                // unique labels per image
__device__ unsigned char      g_map [BB*G];                // g -> unique slot
__device__ int                g_nu  [BB];                  // #unique labels
__device__ unsigned           g_bmp [BB*NWORD];            // prologue-matched bitmap
__device__ unsigned char      g_unmf[BB*G];                // column-unmatched flag
__device__ int                g_nun [BB];                  // #unmatched columns

// =====================================================================
// Kernel 0: per-image label dedup (16 blocks, trivial cost)
// =====================================================================
__global__ void label_map_kernel(const int* __restrict__ labels)
{
    int b = blockIdx.x;
    if (threadIdx.x == 0) {
        int lab[G]; int nu = 0;
        #pragma unroll
        for (int g=0; g<G; g++) lab[g] = labels[b*G+g];
        int ulab[G];
        for (int g=0; g<G; g++) {
            int c = lab[g], slot = -1;
            for (int u=0; u<nu; u++) if (ulab[u]==c) { slot=u; break; }
            if (slot < 0) { slot = nu; ulab[nu++] = c; }
            g_map[b*G+g] = (unsigned char)slot;
        }
        for (int u=0; u<nu; u++) g_ulab[b*G+u] = ulab[u];
        g_nu[b] = nu;
    }
}

// =====================================================================
// Kernel A: warp-per-anchor cost build; precomputed label dedup.
// =====================================================================
#define TBA 512
#define QPB 16
__global__ void __launch_bounds__(TBA)
build_cost_kernel(const float* __restrict__ logits,
                  const float* __restrict__ boxes,
                  const float* __restrict__ gtboxes)
{
    int b = blockIdx.y;
    int qbase = blockIdx.x * QPB;
    int t = threadIdx.x;
    int w = t >> 5, l = t & 31;

    __shared__ float s_gx[G*4];
    __shared__ float s_cx[G], s_cy[G], s_area[G];
    __shared__ int   s_ulab[G];
    __shared__ unsigned char s_map[G];
    __shared__ float s_cost[G][QPB+1];

    if (t < G) {
        float4 gb = ((const float4*)gtboxes)[b*G + t];
        s_cx[t]=gb.x; s_cy[t]=gb.y;
        float x0=gb.x-0.5f*gb.z, y0=gb.y-0.5f*gb.w;
        float x1=gb.x+0.5f*gb.z, y1=gb.y+0.5f*gb.w;
        s_gx[t*4+0]=x0; s_gx[t*4+1]=y0; s_gx[t*4+2]=x1; s_gx[t*4+3]=y1;
        s_area[t]=(x1-x0)*(y1-y0);
        s_ulab[t]=g_ulab[b*G+t];
        s_map[t]=g_map[b*G+t];
    }
    __syncthreads();
    int nu = g_nu[b];

    int q = qbase + w;
    if (q < Q) {
        float4 pb = ((const float4*)boxes)[b*Q + q];
        float ax = pb.x, ay = pb.y;
        float bx0 = pb.x-0.5f*pb.z, by0 = pb.y-0.5f*pb.w;
        float bx1 = pb.x+0.5f*pb.z, by1 = pb.y+0.5f*pb.w;
        float areaA = (bx1-bx0)*(by1-by0);
        const float* lrow = logits + ((long long)b*Q + q)*CC;

        // class cost for unique labels only
        float clsv0 = 0.0f, clsv1 = 0.0f;
        #pragma unroll
        for (int h=0; h<2; h++) {
            int u = l + h*32;
            if (u < nu) {
                float x = __ldg(lrow + s_ulab[u]);
                float p = 1.0f/(1.0f + expf(-x));
                float neg = 0.75f * p*p * (-logf(1.0f - p + 1e-8f));
                float pos = 0.25f * (1.0f-p)*(1.0f-p) * (-logf(p + 1e-8f));
                float cls = pos - neg;
                if (h) clsv1 = cls; else clsv0 = cls;
            }
        }

        float costv[2];
        bool  anyflag = false;
        bool  iibcv[2];
        #pragma unroll
        for (int h=0; h<2; h++) {
            int g = l + h*32;
            bool ib = (ax>s_gx[g*4+0]) && (ax<s_gx[g*4+2]) &&
                      (ay>s_gx[g*4+1]) && (ay<s_gx[g*4+3]);
            bool ic = (ax>s_cx[g]-RADIUS)&&(ax<s_cx[g]+RADIUS)&&
                      (ay>s_cy[g]-RADIUS)&&(ay<s_cy[g]+RADIUS);
            anyflag |= (ib | ic);
            iibcv[h] = ib && ic;
        }
        unsigned ball = __ballot_sync(0xffffffffu, anyflag);
        float fgterm = ball ? 0.0f : 10000.0f;

        #pragma unroll
        for (int h=0; h<2; h++) {
            int g = l + h*32;
            int slot = s_map[g];
            float a0 = __shfl_sync(0xffffffffu, clsv0, slot & 31);
            float a1 = __shfl_sync(0xffffffffu, clsv1, slot & 31);
            float cls = (slot < 32) ? a0 : a1;

            float gx0=s_gx[g*4+0], gy0=s_gx[g*4+1], gx1=s_gx[g*4+2], gy1=s_gx[g*4+3];
            float ltx=fmaxf(bx0,gx0), lty=fmaxf(by0,gy0);
            float rbx=fminf(bx1,gx1), rby=fminf(by1,gy1);
            float iw=fmaxf(rbx-ltx,0.0f), ih=fmaxf(rby-lty,0.0f);
            float inter = iw*ih;
            float uni   = areaA + s_area[g] - inter;
            float iou   = inter/uni;
            float ex0=fminf(bx0,gx0), ey0=fminf(by0,gy0);
            float ex1=fmaxf(bx1,gx1), ey1=fmaxf(by1,gy1);
            float encl = fmaxf(ex1-ex0,0.0f)*fmaxf(ey1-ey0,0.0f);
            float giou = iou - (encl - uni)/encl;

            costv[h] = cls - 3.0f*giou + (iibcv[h] ? 0.0f : 100.0f) + fgterm;
            s_cost[g][w] = costv[h];
        }

        float bv; int bg;
        if (costv[1] < costv[0]) { bv = costv[1]; bg = l+32; }
        else                     { bv = costv[0]; bg = l;    }
        #pragma unroll
        for (int off=16; off; off>>=1) {
            float ov = __shfl_down_sync(0xffffffffu, bv, off);
            int   og = __shfl_down_sync(0xffffffffu, bg, off);
            if (ov < bv || (ov==bv && og < bg)) { bv=ov; bg=og; }
        }
        if (l==0) {
            g_rowarg[b*Q+q] = bg;
            g_mask  [b*Q+q] = 0ULL;
        }
    }
    __syncthreads();

    int r0 = t >> 4, j = t & 15;
    int qq = qbase + j;
    if (qq < Q) {
        float* p = g_cost + ((long long)b*G + r0)*Q + qq;
        #pragma unroll
        for (int r = r0; r < G; r += 32) {
            *p = s_cost[r][j];
            p += (size_t)32*Q;
        }
    }
}

// =====================================================================
// Kernel B: per (b,g) column, single pass; register-resident lists.
// =====================================================================
#define TKB 256
__global__ void __launch_bounds__(TKB)
select_kernel(const float* __restrict__ boxes,
              const float* __restrict__ gtboxes)
{
    int b = blockIdx.x >> 6, g = blockIdx.x & 63;
    const float* cost = g_cost + ((long long)b*G+g)*Q;
    const float4* abox = (const float4*)boxes + (long long)b*Q;
    int t = threadIdx.x;

    float4 gb = __ldg(&((const float4*)gtboxes)[b*G+g]);
    float gx0=gb.x-0.5f*gb.z, gy0=gb.y-0.5f*gb.w;
    float gx1=gb.x+0.5f*gb.z, gy1=gb.y+0.5f*gb.w;
    float areaG=(gx1-gx0)*(gy1-gy0);

    __shared__ float s_pv[TKB*10];
    __shared__ int   s_pi[TKB*10];
    __shared__ int   s_dynk;

    float itop[10];
    float pv[10]; int pi[10];
    #pragma unroll
    for (int i=0;i<10;i++) { itop[i]=-INFINITY; pv[i]=INFINITY; pi[i]=0x7FFFFFFF; }

    for (int q=t; q<Q; q+=TKB) {
        float4 pb = __ldg(abox + q);
        float bx0 = pb.x-0.5f*pb.z, by0 = pb.y-0.5f*pb.w;
        float bx1 = pb.x+0.5f*pb.z, by1 = pb.y+0.5f*pb.w;
        float areaA = (bx1-bx0)*(by1-by0);
        float ltx=fmaxf(bx0,gx0), lty=fmaxf(by0,gy0);
        float rbx=fminf(bx1,gx1), rby=fminf(by1,gy1);
        float iw=fmaxf(rbx-ltx,0.0f), ih=fmaxf(rby-lty,0.0f);
        float inter = iw*ih;
        float uni   = areaA + areaG - inter;
        float iou   = inter/uni;

        if (iou > itop[9]) {
            float nv = iou;
            #pragma unroll
            for (int i=0;i<10;i++) {
                float cur = itop[i];
                bool take = nv > cur;
                itop[i] = take ? nv : cur;
                nv      = take ? cur : nv;
            }
        }
        float v = cost[q];
        if (v < pv[9]) {
            float nv = v; int ni = q;
            #pragma unroll
            for (int i=0;i<10;i++) {
                float cv = pv[i]; int ci = pi[i];
                bool take = (nv < cv) || (nv == cv && ni < ci);
                pv[i] = take ? nv : cv;  pi[i] = take ? ni : ci;
                nv    = take ? cv : nv;  ni    = take ? ci : ni;
            }
        }
    }

    #pragma unroll
    for (int i=0;i<10;i++) s_pv[t*10+i] = itop[i];
    __syncthreads();
    for (int s=TKB/2; s>=1; s>>=1) {
        if (t < s) {
            float a[10], c[10], m[10];
            #pragma unroll
            for (int i=0;i<10;i++){ a[i]=s_pv[t*10+i]; c[i]=s_pv[(t+s)*10+i]; }
            int ia=0, ic=0;
            #pragma unroll
            for (int i=0;i<10;i++) m[i] = (a[ia] >= c[ic]) ? a[ia++] : c[ic++];
            #pragma unroll
            for (int i=0;i<10;i++) s_pv[t*10+i] = m[i];
        }
        __syncthreads();
    }
    if (t==0) {
        float ssum = 0.0f;
        for (int i=0;i<10;i++) ssum += s_pv[i];
        int k = (int)ssum;
        if (k < 1) k = 1;
        if (k > 10) k = 10;
        s_dynk = k;
    }
    __syncthreads();

    #pragma unroll
    for (int i=0;i<10;i++) { s_pv[t*10+i]=pv[i]; s_pi[t*10+i]=pi[i]; }
    __syncthreads();
    for (int s=TKB/2; s>=1; s>>=1) {
        if (t < s) {
            float av[10], bv[10], mv[10];
            int   ai[10], bi[10], mi[10];
            #pragma unroll
            for (int i=0;i<10;i++){
                av[i]=s_pv[t*10+i];     ai[i]=s_pi[t*10+i];
                bv[i]=s_pv[(t+s)*10+i]; bi[i]=s_pi[(t+s)*10+i];
            }
            int ia=0, ic=0;
            #pragma unroll
            for (int i=0;i<10;i++) {
                bool takeA = (av[ia] < bv[ic]) ||
                             (av[ia]==bv[ic] && ai[ia] < bi[ic]);
                if (takeA) { mv[i]=av[ia]; mi[i]=ai[ia]; ia++; }
                else       { mv[i]=bv[ic]; mi[i]=bi[ic]; ic++; }
            }
            #pragma unroll
            for (int i=0;i<10;i++){ s_pv[t*10+i]=mv[i]; s_pi[t*10+i]=mi[i]; }
        }
        __syncthreads();
    }
    if (t==0) {
        int k = s_dynk;
        for (int j=0; j<k; j++)
            atomicOr(&g_mask[b*Q + s_pi[j]], 1ULL<<g);
    }
}

// =====================================================================
// Kernel C1: prep — dedup, matched bitmap, column counts/unmatched flags.
// =====================================================================
#define TDP 1024
__global__ void __launch_bounds__(TDP)
prep_kernel()
{
    int b = blockIdx.x, t = threadIdx.x;
    __shared__ int s_cnt[G];
    __shared__ int s_n;
    if (t < G) s_cnt[t] = 0;
    if (t == 0) s_n = 0;
    __syncthreads();

    // chunk-per-thread: no bitmap atomics
    for (int c=t; c<NWORD; c+=TDP) {
        unsigned word = 0u;
        int q0 = c*32, qe = min(q0+32, Q);
        for (int q=q0; q<qe; q++) {
            unsigned long long m = g_mask[b*Q+q];
            if (__popcll(m) > 1) {
                m = 1ULL << g_rowarg[b*Q+q];
                g_mask[b*Q+q] = m;
            }
            if (m) {
                word |= 1u << (q-q0);
                unsigned long long mm = m;
                while (mm) { int g = __ffsll((long long)mm)-1; atomicAdd(&s_cnt[g],1); mm &= mm-1; }
            }
        }
        g_bmp[b*NWORD + c] = word;
    }
    __syncthreads();
    if (t < G) {
        int un = (s_cnt[t] == 0) ? 1 : 0;
        g_unmf[b*G+t] = (unsigned char)un;
        if (un) atomicAdd(&s_n, 1);
    }
    __syncthreads();
    if (t == 0) g_nun[b] = s_n;
}

// =====================================================================
// Kernel C2: colmin — one block per (b,g); unmatched columns do a
// block-parallel argmin over rows NOT in the matched bitmap.
// =====================================================================
#define TCM 256
__global__ void __launch_bounds__(TCM)
colmin_kernel()
{
    int b = blockIdx.x >> 6, g = blockIdx.x & 63;
    if (!g_unmf[b*G+g]) return;
    int t = threadIdx.x;
    const float4* cg4 = (const float4*)(g_cost + ((long long)b*G+g)*Q);
    const unsigned* bmp = g_bmp + b*NWORD;

    __shared__ float s_rv[TCM];
    __shared__ int   s_ri[TCM];

    float bv = INFINITY; int bi = Q;
    for (int i=t; i<Q4; i+=TCM) {
        unsigned nib = (bmp[i>>3] >> ((i&7)*4)) & 0xFu;
        float4 c = __ldg(cg4 + i);
        int q0 = i*4;
        if (!(nib & 1u) && c.x < bv) { bv=c.x; bi=q0;   }
        if (!(nib & 2u) && c.y < bv) { bv=c.y; bi=q0+1; }
        if (!(nib & 4u) && c.z < bv) { bv=c.z; bi=q0+2; }
        if (!(nib & 8u) && c.w < bv) { bv=c.w; bi=q0+3; }
    }
    s_rv[t]=bv; s_ri[t]=bi;
    __syncthreads();
    for (int s=TCM/2; s>=1; s>>=1) {
        if (t < s) {
            float ov=s_rv[t+s]; int oi=s_ri[t+s];
            if (ov < s_rv[t] || (ov==s_rv[t] && oi < s_ri[t])) { s_rv[t]=ov; s_ri[t]=oi; }
        }
        __syncthreads();
    }
    if (t==0 && s_ri[0] < Q)
        atomicOr(&g_mask[b*Q + s_ri[0]], 1ULL<<g);
}

// =====================================================================
// Kernel C3: output — sel/asn per row; out_mq via packed smem atomicMin
// over matched entries only (O(matched), not O(G*Q)).
// =====================================================================
#define TDO 1024
__device__ __forceinline__ unsigned ordf(float v) {
    unsigned u = __float_as_uint(v);
    return (u & 0x80000000u) ? ~u : (u | 0x80000000u);
}
__global__ void __launch_bounds__(TDO)
output_kernel(char* __restrict__ out_bytes, int layoutB)
{
    int b = blockIdx.x, t = threadIdx.x;
    const float* cost = g_cost + (long long)b*G*Q;
    const unsigned* bmp = g_bmp + b*NWORD;
    float penT = (g_nun[b] > 0) ? 100000.0f : 0.0f;

    __shared__ unsigned long long s_pk[G];
    if (t < G) s_pk[t] = 0xFFFFFFFFFFFFFFFFULL;
    __syncthreads();

    unsigned char* out_sel8 = (unsigned char*)out_bytes;
    int*   out_asnI = (int*)(out_bytes + (size_t)BB*Q);
    int*   out_mqI  = (int*)(out_bytes + (size_t)BB*Q + (size_t)4*BB*Q);
    float* outF     = (float*)out_bytes;

    for (int q=t; q<Q; q+=TDO) {
        unsigned long long m = g_mask[b*Q+q];
        if (layoutB) {
            out_sel8[b*Q+q] = m ? 1 : 0;
            out_asnI[b*Q+q] = m ? (__ffsll((long long)m)-1) : 0;
        } else {
            outF[b*Q+q]        = m ? 1.0f : 0.0f;
            outF[BB*Q + b*Q+q] = m ? (float)(__ffsll((long long)m)-1) : 0.0f;
        }
        if (m) {
            float pen = ((bmp[q>>5] >> (q&31)) & 1u) ? penT : 0.0f;
            unsigned long long mm = m;
            while (mm) {
                int g = __ffsll((long long)mm)-1; mm &= mm-1;
                float v = cost[(long long)g*Q + q] + pen;
                unsigned long long pk = ((unsigned long long)ordf(v) << 32) | (unsigned)q;
                atomicMin(&s_pk[g], pk);
            }
        }
    }
    __syncthreads();
    if (t < G) {
        int qmin = (int)(s_pk[t] & 0xFFFFFFFFULL);
        if (layoutB) out_mqI[b*G+t] = qmin;
        else         outF[2*BB*Q + b*G+t] = (float)qmin;
    }
}

// =====================================================================
extern "C" void kernel_launch(void* const* d_in, const int* in_sizes, int n_in,
                              void* d_out, int out_size)
{
    const float* logits = 0; const float* boxes = 0;
    const int*   labels = 0; const float* gtb   = 0;
    for (int i = 0; i < n_in; i++) {
        switch (in_sizes[i]) {
            case BB*Q*CC: logits = (const float*)d_in[i]; break;
            case BB*Q*4:  boxes  = (const float*)d_in[i]; break;
            case BB*G:    labels = (const int*)  d_in[i]; break;
            case BB*G*4:  gtb    = (const float*)d_in[i]; break;
        }
    }

    int layoutB = (out_size == BB*Q + 4*BB*Q + 4*BB*G) ? 1 : 0;

    label_map_kernel<<<BB, 32>>>(labels);
    dim3 gA((Q + QPB - 1)/QPB, BB);
    build_cost_kernel<<<gA, TBA>>>(logits, boxes, gtb);
    select_kernel<<<BB*G, TKB>>>(boxes, gtb);
    prep_kernel<<<BB, TDP>>>();
    colmin_kernel<<<BB*G, TCM>>>();
    output_kernel<<<BB, TDO>>>((char*)d_out, layoutB);
}

// round 9
// speedup vs baseline: 1.5385x; 1.3755x over previous
#include <cuda_runtime.h>
#include <math.h>

#define BB 16
#define Q  8400
#define CC 80
#define G  64
#define RADIUS (2.5f/32.0f)
#define NWORD ((Q+31)/32)
#define Q4 (Q/4)

// ---- scratch (static device globals; no runtime allocation) ----
__device__ float              g_cost[(long long)BB*G*Q];   // [b][g][q]
__device__ unsigned long long g_mask[BB*Q];                // per-anchor GT bitmask
__device__ int                g_rowarg[BB*Q];              // argmin_g cost0[q][g]
__device__ unsigned           g_bmp [BB*NWORD];            // prologue-matched bitmap
__device__ unsigned char      g_unmf[BB*G];                // column-unmatched flag
__device__ int                g_nun [BB];                  // #unmatched columns

// =====================================================================
// Kernel A: warp-per-anchor cost build (proven 78us form; float4 LDS).
// =====================================================================
#define TBA 512
#define QPB 16
__global__ void __launch_bounds__(TBA)
build_cost_kernel(const float* __restrict__ logits,
                  const float* __restrict__ boxes,
                  const int*   __restrict__ labels,
                  const float* __restrict__ gtboxes)
{
    int b = blockIdx.y;
    int qbase = blockIdx.x * QPB;
    int t = threadIdx.x;
    int w = t >> 5, l = t & 31;

    __shared__ float4 s_gx4[G];      // gt xyxy packed
    __shared__ float  s_cx[G], s_cy[G], s_area[G];
    __shared__ int    s_lab[G];
    __shared__ float  s_cost[G][QPB+1];

    if (t < G) {
        float4 gb = ((const float4*)gtboxes)[b*G + t];
        s_cx[t]=gb.x; s_cy[t]=gb.y;
        float x0=gb.x-0.5f*gb.z, y0=gb.y-0.5f*gb.w;
        float x1=gb.x+0.5f*gb.z, y1=gb.y+0.5f*gb.w;
        s_gx4[t] = make_float4(x0,y0,x1,y1);
        s_area[t]=(x1-x0)*(y1-y0);
        s_lab[t]=labels[b*G+t];
    }
    __syncthreads();

    int q = qbase + w;
    if (q < Q) {
        float4 pb = ((const float4*)boxes)[b*Q + q];
        float ax = pb.x, ay = pb.y;
        float bx0 = pb.x-0.5f*pb.z, by0 = pb.y-0.5f*pb.w;
        float bx1 = pb.x+0.5f*pb.z, by1 = pb.y+0.5f*pb.w;
        float areaA = (bx1-bx0)*(by1-by0);
        const float* lrow = logits + ((long long)b*Q + q)*CC;

        float costv[2];
        bool  anyflag = false;
        bool  iibcv[2];

        #pragma unroll
        for (int h=0; h<2; h++) {
            int g = l + h*32;
            float4 gx = s_gx4[g];
            bool ib = (ax>gx.x) && (ax<gx.z) && (ay>gx.y) && (ay<gx.w);
            bool ic = (ax>s_cx[g]-RADIUS)&&(ax<s_cx[g]+RADIUS)&&
                      (ay>s_cy[g]-RADIUS)&&(ay<s_cy[g]+RADIUS);
            anyflag |= (ib | ic);
            iibcv[h] = ib && ic;
        }
        unsigned ball = __ballot_sync(0xffffffffu, anyflag);
        float fgterm = ball ? 0.0f : 10000.0f;

        #pragma unroll
        for (int h=0; h<2; h++) {
            int g = l + h*32;
            float x = __ldg(lrow + s_lab[g]);
            float p = 1.0f/(1.0f + expf(-x));
            float neg = 0.75f * p*p * (-logf(1.0f - p + 1e-8f));
            float pos = 0.25f * (1.0f-p)*(1.0f-p) * (-logf(p + 1e-8f));
            float cls = pos - neg;

            float4 gx = s_gx4[g];
            float ltx=fmaxf(bx0,gx.x), lty=fmaxf(by0,gx.y);
            float rbx=fminf(bx1,gx.z), rby=fminf(by1,gx.w);
            float iw=fmaxf(rbx-ltx,0.0f), ih=fmaxf(rby-lty,0.0f);
            float inter = iw*ih;
            float uni   = areaA + s_area[g] - inter;
            float iou   = inter/uni;
            float ex0=fminf(bx0,gx.x), ey0=fminf(by0,gx.y);
            float ex1=fmaxf(bx1,gx.z), ey1=fmaxf(by1,gx.w);
            float encl = fmaxf(ex1-ex0,0.0f)*fmaxf(ey1-ey0,0.0f);
            float giou = iou - (encl - uni)/encl;

            costv[h] = cls - 3.0f*giou + (iibcv[h] ? 0.0f : 100.0f) + fgterm;
            s_cost[g][w] = costv[h];
        }

        float bv; int bg;
        if (costv[1] < costv[0]) { bv = costv[1]; bg = l+32; }
        else                     { bv = costv[0]; bg = l;    }
        #pragma unroll
        for (int off=16; off; off>>=1) {
            float ov = __shfl_down_sync(0xffffffffu, bv, off);
            int   og = __shfl_down_sync(0xffffffffu, bg, off);
            if (ov < bv || (ov==bv && og < bg)) { bv=ov; bg=og; }
        }
        if (l==0) {
            g_rowarg[b*Q+q] = bg;
            g_mask  [b*Q+q] = 0ULL;
        }
    }
    __syncthreads();

    int r0 = t >> 4, j = t & 15;
    int qq = qbase + j;
    if (qq < Q) {
        float* p = g_cost + ((long long)b*G + r0)*Q + qq;
        #pragma unroll
        for (int r = r0; r < G; r += 32) {
            *p = s_cost[r][j];
            p += (size_t)32*Q;
        }
    }
}

// =====================================================================
// Kernel B: per (b,g) column, single pass; register-resident lists.
// =====================================================================
#define TKB 256
__global__ void __launch_bounds__(TKB)
select_kernel(const float* __restrict__ boxes,
              const float* __restrict__ gtboxes)
{
    int b = blockIdx.x >> 6, g = blockIdx.x & 63;
    const float* cost = g_cost + ((long long)b*G+g)*Q;
    const float4* abox = (const float4*)boxes + (long long)b*Q;
    int t = threadIdx.x;

    float4 gb = __ldg(&((const float4*)gtboxes)[b*G+g]);
    float gx0=gb.x-0.5f*gb.z, gy0=gb.y-0.5f*gb.w;
    float gx1=gb.x+0.5f*gb.z, gy1=gb.y+0.5f*gb.w;
    float areaG=(gx1-gx0)*(gy1-gy0);

    __shared__ float s_pv[TKB*10];
    __shared__ int   s_pi[TKB*10];
    __shared__ int   s_dynk;

    float itop[10];
    float pv[10]; int pi[10];
    #pragma unroll
    for (int i=0;i<10;i++) { itop[i]=-INFINITY; pv[i]=INFINITY; pi[i]=0x7FFFFFFF; }

    for (int q=t; q<Q; q+=TKB) {
        float4 pb = __ldg(abox + q);
        float bx0 = pb.x-0.5f*pb.z, by0 = pb.y-0.5f*pb.w;
        float bx1 = pb.x+0.5f*pb.z, by1 = pb.y+0.5f*pb.w;
        float areaA = (bx1-bx0)*(by1-by0);
        float ltx=fmaxf(bx0,gx0), lty=fmaxf(by0,gy0);
        float rbx=fminf(bx1,gx1), rby=fminf(by1,gy1);
        float iw=fmaxf(rbx-ltx,0.0f), ih=fmaxf(rby-lty,0.0f);
        float inter = iw*ih;
        float uni   = areaA + areaG - inter;
        float iou   = inter/uni;

        if (iou > itop[9]) {
            float nv = iou;
            #pragma unroll
            for (int i=0;i<10;i++) {
                float cur = itop[i];
                bool take = nv > cur;
                itop[i] = take ? nv : cur;
                nv      = take ? cur : nv;
            }
        }
        float v = cost[q];
        if (v < pv[9]) {
            float nv = v; int ni = q;
            #pragma unroll
            for (int i=0;i<10;i++) {
                float cv = pv[i]; int ci = pi[i];
                bool take = (nv < cv) || (nv == cv && ni < ci);
                pv[i] = take ? nv : cv;  pi[i] = take ? ni : ci;
                nv    = take ? cv : nv;  ni    = take ? ci : ni;
            }
        }
    }

    #pragma unroll
    for (int i=0;i<10;i++) s_pv[t*10+i] = itop[i];
    __syncthreads();
    for (int s=TKB/2; s>=1; s>>=1) {
        if (t < s) {
            float a[10], c[10], m[10];
            #pragma unroll
            for (int i=0;i<10;i++){ a[i]=s_pv[t*10+i]; c[i]=s_pv[(t+s)*10+i]; }
            int ia=0, ic=0;
            #pragma unroll
            for (int i=0;i<10;i++) m[i] = (a[ia] >= c[ic]) ? a[ia++] : c[ic++];
            #pragma unroll
            for (int i=0;i<10;i++) s_pv[t*10+i] = m[i];
        }
        __syncthreads();
    }
    if (t==0) {
        float ssum = 0.0f;
        for (int i=0;i<10;i++) ssum += s_pv[i];
        int k = (int)ssum;
        if (k < 1) k = 1;
        if (k > 10) k = 10;
        s_dynk = k;
    }
    __syncthreads();

    #pragma unroll
    for (int i=0;i<10;i++) { s_pv[t*10+i]=pv[i]; s_pi[t*10+i]=pi[i]; }
    __syncthreads();
    for (int s=TKB/2; s>=1; s>>=1) {
        if (t < s) {
            float av[10], bv[10], mv[10];
            int   ai[10], bi[10], mi[10];
            #pragma unroll
            for (int i=0;i<10;i++){
                av[i]=s_pv[t*10+i];     ai[i]=s_pi[t*10+i];
                bv[i]=s_pv[(t+s)*10+i]; bi[i]=s_pi[(t+s)*10+i];
            }
            int ia=0, ic=0;
            #pragma unroll
            for (int i=0;i<10;i++) {
                bool takeA = (av[ia] < bv[ic]) ||
                             (av[ia]==bv[ic] && ai[ia] < bi[ic]);
                if (takeA) { mv[i]=av[ia]; mi[i]=ai[ia]; ia++; }
                else       { mv[i]=bv[ic]; mi[i]=bi[ic]; ic++; }
            }
            #pragma unroll
            for (int i=0;i<10;i++){ s_pv[t*10+i]=mv[i]; s_pi[t*10+i]=mi[i]; }
        }
        __syncthreads();
    }
    if (t==0) {
        int k = s_dynk;
        for (int j=0; j<k; j++)
            atomicOr(&g_mask[b*Q + s_pi[j]], 1ULL<<g);
    }
}

// =====================================================================
// Kernel C1: prep — thread-per-row dedup + ballot bitmap + counts.
// =====================================================================
#define TDP 1024
__global__ void __launch_bounds__(TDP)
prep_kernel()
{
    int b = blockIdx.x, t = threadIdx.x;
    int lane = t & 31;
    __shared__ int s_cnt[G];
    __shared__ int s_n;
    if (t < G) s_cnt[t] = 0;
    if (t == 0) s_n = 0;
    __syncthreads();

    // uniform trip count so ballot masks stay full
    for (int q0 = 0; q0 < NWORD*32; q0 += TDP) {
        int q = q0 + t;
        bool matched = false;
        if (q < Q) {
            unsigned long long m = g_mask[b*Q+q];
            if (__popcll(m) > 1) {
                m = 1ULL << g_rowarg[b*Q+q];
                g_mask[b*Q+q] = m;
            }
            if (m) {
                matched = true;
                unsigned long long mm = m;
                while (mm) { int g = __ffsll((long long)mm)-1; atomicAdd(&s_cnt[g],1); mm &= mm-1; }
            }
        }
        unsigned word = __ballot_sync(0xffffffffu, matched);
        int widx = q >> 5;
        if (lane == 0 && widx < NWORD) g_bmp[b*NWORD + widx] = word;
    }
    __syncthreads();
    if (t < G) {
        int un = (s_cnt[t] == 0) ? 1 : 0;
        g_unmf[b*G+t] = (unsigned char)un;
        if (un) atomicAdd(&s_n, 1);
    }
    __syncthreads();
    if (t == 0) g_nun[b] = s_n;
}

// =====================================================================
// Kernel C2: colmin — one block per (b,g); unmatched columns only.
// =====================================================================
#define TCM 256
__global__ void __launch_bounds__(TCM)
colmin_kernel()
{
    int b = blockIdx.x >> 6, g = blockIdx.x & 63;
    if (!g_unmf[b*G+g]) return;
    int t = threadIdx.x;
    const float4* cg4 = (const float4*)(g_cost + ((long long)b*G+g)*Q);
    const unsigned* bmp = g_bmp + b*NWORD;

    __shared__ float s_rv[TCM];
    __shared__ int   s_ri[TCM];

    float bv = INFINITY; int bi = Q;
    for (int i=t; i<Q4; i+=TCM) {
        unsigned nib = (bmp[i>>3] >> ((i&7)*4)) & 0xFu;
        float4 c = __ldg(cg4 + i);
        int q0 = i*4;
        if (!(nib & 1u) && c.x < bv) { bv=c.x; bi=q0;   }
        if (!(nib & 2u) && c.y < bv) { bv=c.y; bi=q0+1; }
        if (!(nib & 4u) && c.z < bv) { bv=c.z; bi=q0+2; }
        if (!(nib & 8u) && c.w < bv) { bv=c.w; bi=q0+3; }
    }
    s_rv[t]=bv; s_ri[t]=bi;
    __syncthreads();
    for (int s=TCM/2; s>=1; s>>=1) {
        if (t < s) {
            float ov=s_rv[t+s]; int oi=s_ri[t+s];
            if (ov < s_rv[t] || (ov==s_rv[t] && oi < s_ri[t])) { s_rv[t]=ov; s_ri[t]=oi; }
        }
        __syncthreads();
    }
    if (t==0 && s_ri[0] < Q)
        atomicOr(&g_mask[b*Q + s_ri[0]], 1ULL<<g);
}

// =====================================================================
// Kernel C3: output — sel/asn per row; out_mq via packed smem atomicMin.
// =====================================================================
#define TDO 1024
__device__ __forceinline__ unsigned ordf(float v) {
    unsigned u = __float_as_uint(v);
    return (u & 0x80000000u) ? ~u : (u | 0x80000000u);
}
__global__ void __launch_bounds__(TDO)
output_kernel(char* __restrict__ out_bytes, int layoutB)
{
    int b = blockIdx.x, t = threadIdx.x;
    const float* cost = g_cost + (long long)b*G*Q;
    const unsigned* bmp = g_bmp + b*NWORD;
    float penT = (g_nun[b] > 0) ? 100000.0f : 0.0f;

    __shared__ unsigned long long s_pk[G];
    if (t < G) s_pk[t] = 0xFFFFFFFFFFFFFFFFULL;
    __syncthreads();

    unsigned char* out_sel8 = (unsigned char*)out_bytes;
    int*   out_asnI = (int*)(out_bytes + (size_t)BB*Q);
    int*   out_mqI  = (int*)(out_bytes + (size_t)BB*Q + (size_t)4*BB*Q);
    float* outF     = (float*)out_bytes;

    for (int q=t; q<Q; q+=TDO) {
        unsigned long long m = g_mask[b*Q+q];
        if (layoutB) {
            out_sel8[b*Q+q] = m ? 1 : 0;
            out_asnI[b*Q+q] = m ? (__ffsll((long long)m)-1) : 0;
        } else {
            outF[b*Q+q]        = m ? 1.0f : 0.0f;
            outF[BB*Q + b*Q+q] = m ? (float)(__ffsll((long long)m)-1) : 0.0f;
        }
        if (m) {
            float pen = ((bmp[q>>5] >> (q&31)) & 1u) ? penT : 0.0f;
            unsigned long long mm = m;
            while (mm) {
                int g = __ffsll((long long)mm)-1; mm &= mm-1;
                float v = cost[(long long)g*Q + q] + pen;
                unsigned long long pk = ((unsigned long long)ordf(v) << 32) | (unsigned)q;
                atomicMin(&s_pk[g], pk);
            }
        }
    }
    __syncthreads();
    if (t < G) {
        int qmin = (int)(s_pk[t] & 0xFFFFFFFFULL);
        if (layoutB) out_mqI[b*G+t] = qmin;
        else         outF[2*BB*Q + b*G+t] = (float)qmin;
    }
}

// =====================================================================
extern "C" void kernel_launch(void* const* d_in, const int* in_sizes, int n_in,
                              void* d_out, int out_size)
{
    const float* logits = 0; const float* boxes = 0;
    const int*   labels = 0; const float* gtb   = 0;
    for (int i = 0; i < n_in; i++) {
        switch (in_sizes[i]) {
            case BB*Q*CC: logits = (const float*)d_in[i]; break;
            case BB*Q*4:  boxes  = (const float*)d_in[i]; break;
            case BB*G:    labels = (const int*)  d_in[i]; break;
            case BB*G*4:  gtb    = (const float*)d_in[i]; break;
        }
    }

    int layoutB = (out_size == BB*Q + 4*BB*Q + 4*BB*G) ? 1 : 0;

    dim3 gA((Q + QPB - 1)/QPB, BB);
    build_cost_kernel<<<gA, TBA>>>(logits, boxes, labels, gtb);
    select_kernel<<<BB*G, TKB>>>(boxes, gtb);
    prep_kernel<<<BB, TDP>>>();
    colmin_kernel<<<BB*G, TCM>>>();
    output_kernel<<<BB, TDO>>>((char*)d_out, layoutB);
}

// round 10
// speedup vs baseline: 1.9386x; 1.2600x over previous
#include <cuda_runtime.h>
#include <math.h>

#define BB 16
#define Q  8400
#define CC 80
#define G  64
#define RADIUS (2.5f/32.0f)
#define NWORD ((Q+31)/32)
#define Q4 (Q/4)

// ---- scratch (static device globals; no runtime allocation) ----
__device__ float              g_cost[(long long)BB*G*Q];   // [b][g][q]
__device__ unsigned long long g_mask[BB*Q];                // per-anchor GT bitmask
__device__ int                g_rowarg[BB*Q];              // argmin_g cost0[q][g]
__device__ unsigned           g_bmp [BB*NWORD];            // prologue-matched bitmap
__device__ unsigned char      g_unmf[BB*G];                // column-unmatched flag
__device__ int                g_nun [BB];                  // #unmatched columns

// =====================================================================
// Kernel A: warp-per-anchor cost build; fast transcendentals.
// =====================================================================
#define TBA 512
#define QPB 16
__global__ void __launch_bounds__(TBA)
build_cost_kernel(const float* __restrict__ logits,
                  const float* __restrict__ boxes,
                  const int*   __restrict__ labels,
                  const float* __restrict__ gtboxes)
{
    int b = blockIdx.y;
    int qbase = blockIdx.x * QPB;
    int t = threadIdx.x;
    int w = t >> 5, l = t & 31;

    __shared__ float4 s_gx4[G];
    __shared__ float  s_cx[G], s_cy[G], s_area[G];
    __shared__ int    s_lab[G];
    __shared__ float  s_cost[G][QPB+1];

    if (t < G) {
        float4 gb = ((const float4*)gtboxes)[b*G + t];
        s_cx[t]=gb.x; s_cy[t]=gb.y;
        float x0=gb.x-0.5f*gb.z, y0=gb.y-0.5f*gb.w;
        float x1=gb.x+0.5f*gb.z, y1=gb.y+0.5f*gb.w;
        s_gx4[t] = make_float4(x0,y0,x1,y1);
        s_area[t]=(x1-x0)*(y1-y0);
        s_lab[t]=labels[b*G+t];
    }
    __syncthreads();

    int q = qbase + w;
    if (q < Q) {
        float4 pb = ((const float4*)boxes)[b*Q + q];
        float ax = pb.x, ay = pb.y;
        float bx0 = pb.x-0.5f*pb.z, by0 = pb.y-0.5f*pb.w;
        float bx1 = pb.x+0.5f*pb.z, by1 = pb.y+0.5f*pb.w;
        float areaA = (bx1-bx0)*(by1-by0);
        const float* lrow = logits + ((long long)b*Q + q)*CC;

        float costv[2];
        bool  anyflag = false;
        bool  iibcv[2];

        #pragma unroll
        for (int h=0; h<2; h++) {
            int g = l + h*32;
            float4 gx = s_gx4[g];
            bool ib = (ax>gx.x) && (ax<gx.z) && (ay>gx.y) && (ay<gx.w);
            bool ic = (ax>s_cx[g]-RADIUS)&&(ax<s_cx[g]+RADIUS)&&
                      (ay>s_cy[g]-RADIUS)&&(ay<s_cy[g]+RADIUS);
            anyflag |= (ib | ic);
            iibcv[h] = ib && ic;
        }
        unsigned ball = __ballot_sync(0xffffffffu, anyflag);
        float fgterm = ball ? 0.0f : 10000.0f;

        #pragma unroll
        for (int h=0; h<2; h++) {
            int g = l + h*32;
            float x = __ldg(lrow + s_lab[g]);
            float p = __fdividef(1.0f, 1.0f + __expf(-x));
            float neg = 0.75f * p*p * (-__logf(1.0f - p + 1e-8f));
            float pos = 0.25f * (1.0f-p)*(1.0f-p) * (-__logf(p + 1e-8f));
            float cls = pos - neg;

            float4 gx = s_gx4[g];
            float ltx=fmaxf(bx0,gx.x), lty=fmaxf(by0,gx.y);
            float rbx=fminf(bx1,gx.z), rby=fminf(by1,gx.w);
            float iw=fmaxf(rbx-ltx,0.0f), ih=fmaxf(rby-lty,0.0f);
            float inter = iw*ih;
            float uni   = areaA + s_area[g] - inter;
            float iou   = __fdividef(inter, uni);
            float ex0=fminf(bx0,gx.x), ey0=fminf(by0,gx.y);
            float ex1=fmaxf(bx1,gx.z), ey1=fmaxf(by1,gx.w);
            float encl = fmaxf(ex1-ex0,0.0f)*fmaxf(ey1-ey0,0.0f);
            float giou = iou - __fdividef(encl - uni, encl);

            costv[h] = cls - 3.0f*giou + (iibcv[h] ? 0.0f : 100.0f) + fgterm;
            s_cost[g][w] = costv[h];
        }

        float bv; int bg;
        if (costv[1] < costv[0]) { bv = costv[1]; bg = l+32; }
        else                     { bv = costv[0]; bg = l;    }
        #pragma unroll
        for (int off=16; off; off>>=1) {
            float ov = __shfl_down_sync(0xffffffffu, bv, off);
            int   og = __shfl_down_sync(0xffffffffu, bg, off);
            if (ov < bv || (ov==bv && og < bg)) { bv=ov; bg=og; }
        }
        if (l==0) {
            g_rowarg[b*Q+q] = bg;
            g_mask  [b*Q+q] = 0ULL;
        }
    }
    __syncthreads();

    int r0 = t >> 4, j = t & 15;
    int qq = qbase + j;
    if (qq < Q) {
        float* p = g_cost + ((long long)b*G + r0)*Q + qq;
        #pragma unroll
        for (int r = r0; r < G; r += 32) {
            *p = s_cost[r][j];
            p += (size_t)32*Q;
        }
    }
}

// =====================================================================
// Kernel B: per (b,g) column select; register-resident scan lists AND
// register-resident merges (valley combine + static odd-even network).
// =====================================================================
#define TKB 256
__global__ void __launch_bounds__(TKB)
select_kernel(const float* __restrict__ boxes,
              const float* __restrict__ gtboxes)
{
    int b = blockIdx.x >> 6, g = blockIdx.x & 63;
    const float* cost = g_cost + ((long long)b*G+g)*Q;
    const float4* abox = (const float4*)boxes + (long long)b*Q;
    int t = threadIdx.x;

    float4 gb = __ldg(&((const float4*)gtboxes)[b*G+g]);
    float gx0=gb.x-0.5f*gb.z, gy0=gb.y-0.5f*gb.w;
    float gx1=gb.x+0.5f*gb.z, gy1=gb.y+0.5f*gb.w;
    float areaG=(gx1-gx0)*(gy1-gy0);

    __shared__ float s_iv[TKB*10];
    __shared__ float s_pv[TKB*10];
    __shared__ int   s_pi[TKB*10];

    float itop[10];
    float pv[10]; int pi[10];
    #pragma unroll
    for (int i=0;i<10;i++) { itop[i]=-INFINITY; pv[i]=INFINITY; pi[i]=0x7FFFFFFF; }

    // ---- scan ----
    for (int q=t; q<Q; q+=TKB) {
        float4 pb = __ldg(abox + q);
        float bx0 = pb.x-0.5f*pb.z, by0 = pb.y-0.5f*pb.w;
        float bx1 = pb.x+0.5f*pb.z, by1 = pb.y+0.5f*pb.w;
        float areaA = (bx1-bx0)*(by1-by0);
        float ltx=fmaxf(bx0,gx0), lty=fmaxf(by0,gy0);
        float rbx=fminf(bx1,gx1), rby=fminf(by1,gy1);
        float iw=fmaxf(rbx-ltx,0.0f), ih=fmaxf(rby-lty,0.0f);
        float inter = iw*ih;
        float uni   = areaA + areaG - inter;
        float iou   = __fdividef(inter, uni);

        if (iou > itop[9]) {
            float nv = iou;
            #pragma unroll
            for (int i=0;i<10;i++) {
                float cur = itop[i];
                bool take = nv > cur;
                itop[i] = take ? nv : cur;
                nv      = take ? cur : nv;
            }
        }
        float v = cost[q];
        if (v < pv[9]) {
            float nv = v; int ni = q;
            #pragma unroll
            for (int i=0;i<10;i++) {
                float cv = pv[i]; int ci = pi[i];
                bool take = (nv < cv) || (nv == cv && ni < ci);
                pv[i] = take ? nv : cv;  pi[i] = take ? ni : ci;
                nv    = take ? cv : nv;  ni    = take ? ci : ni;
            }
        }
    }

    // publish initial lists
    #pragma unroll
    for (int i=0;i<10;i++) {
        s_iv[t*10+i]=itop[i]; s_pv[t*10+i]=pv[i]; s_pi[t*10+i]=pi[i];
    }
    __syncthreads();

    // ---- tree merge, registers only ----
    for (int s=TKB/2; s>=1; s>>=1) {
        if (t < s) {
            int o = (t+s)*10;
            // iou: top-10 of union via valley combine, then sort desc
            float ci[10];
            #pragma unroll
            for (int i=0;i<10;i++) ci[i] = fmaxf(itop[i], s_iv[o+9-i]);
            #pragma unroll
            for (int r=0;r<10;r++) {
                #pragma unroll
                for (int i=0;i<9;i++) {
                    if (((i^r)&1)==0) {
                        float a=ci[i], c2=ci[i+1];
                        ci[i]=fmaxf(a,c2); ci[i+1]=fminf(a,c2);
                    }
                }
            }
            #pragma unroll
            for (int i=0;i<10;i++) itop[i]=ci[i];

            // (cost,idx): bottom-10 lex via valley combine, then sort asc-lex
            float cv[10]; int cx[10];
            #pragma unroll
            for (int i=0;i<10;i++) {
                float ov2 = s_pv[o+9-i]; int oi2 = s_pi[o+9-i];
                bool mineWins = (pv[i] < ov2) || (pv[i]==ov2 && pi[i] < oi2);
                cv[i] = mineWins ? pv[i] : ov2;
                cx[i] = mineWins ? pi[i] : oi2;
            }
            #pragma unroll
            for (int r=0;r<10;r++) {
                #pragma unroll
                for (int i=0;i<9;i++) {
                    if (((i^r)&1)==0) {
                        float a=cv[i], c2=cv[i+1];
                        int   ai=cx[i], ci2=cx[i+1];
                        bool sw = (a > c2) || (a==c2 && ai > ci2);
                        cv[i]   = sw ? c2 : a;   cv[i+1] = sw ? a  : c2;
                        cx[i]   = sw ? ci2: ai;  cx[i+1] = sw ? ai : ci2;
                    }
                }
            }
            #pragma unroll
            for (int i=0;i<10;i++) { pv[i]=cv[i]; pi[i]=cx[i]; }

            // re-publish for next stage
            #pragma unroll
            for (int i=0;i<10;i++) {
                s_iv[t*10+i]=itop[i]; s_pv[t*10+i]=pv[i]; s_pi[t*10+i]=pi[i];
            }
        }
        __syncthreads();
    }

    if (t==0) {
        float ssum = 0.0f;
        #pragma unroll
        for (int i=0;i<10;i++) ssum += itop[i];
        int k = (int)ssum;
        if (k < 1) k = 1;
        if (k > 10) k = 10;
        for (int j=0; j<k; j++)
            atomicOr(&g_mask[b*Q + pi[j]], 1ULL<<g);
    }
}

// =====================================================================
// Kernel C1: prep — thread-per-row dedup + ballot bitmap + counts.
// =====================================================================
#define TDP 1024
__global__ void __launch_bounds__(TDP)
prep_kernel()
{
    int b = blockIdx.x, t = threadIdx.x;
    int lane = t & 31;
    __shared__ int s_cnt[G];
    __shared__ int s_n;
    if (t < G) s_cnt[t] = 0;
    if (t == 0) s_n = 0;
    __syncthreads();

    for (int q0 = 0; q0 < NWORD*32; q0 += TDP) {
        int q = q0 + t;
        bool matched = false;
        if (q < Q) {
            unsigned long long m = g_mask[b*Q+q];
            if (__popcll(m) > 1) {
                m = 1ULL << g_rowarg[b*Q+q];
                g_mask[b*Q+q] = m;
            }
            if (m) {
                matched = true;
                unsigned long long mm = m;
                while (mm) { int g = __ffsll((long long)mm)-1; atomicAdd(&s_cnt[g],1); mm &= mm-1; }
            }
        }
        unsigned word = __ballot_sync(0xffffffffu, matched);
        int widx = q >> 5;
        if (lane == 0 && widx < NWORD) g_bmp[b*NWORD + widx] = word;
    }
    __syncthreads();
    if (t < G) {
        int un = (s_cnt[t] == 0) ? 1 : 0;
        g_unmf[b*G+t] = (unsigned char)un;
        if (un) atomicAdd(&s_n, 1);
    }
    __syncthreads();
    if (t == 0) g_nun[b] = s_n;
}

// =====================================================================
// Kernel C2: colmin — one block per (b,g); unmatched columns only.
// =====================================================================
#define TCM 256
__global__ void __launch_bounds__(TCM)
colmin_kernel()
{
    int b = blockIdx.x >> 6, g = blockIdx.x & 63;
    if (!g_unmf[b*G+g]) return;
    int t = threadIdx.x;
    const float4* cg4 = (const float4*)(g_cost + ((long long)b*G+g)*Q);
    const unsigned* bmp = g_bmp + b*NWORD;

    __shared__ float s_rv[TCM];
    __shared__ int   s_ri[TCM];

    float bv = INFINITY; int bi = Q;
    for (int i=t; i<Q4; i+=TCM) {
        unsigned nib = (bmp[i>>3] >> ((i&7)*4)) & 0xFu;
        float4 c = __ldg(cg4 + i);
        int q0 = i*4;
        if (!(nib & 1u) && c.x < bv) { bv=c.x; bi=q0;   }
        if (!(nib & 2u) && c.y < bv) { bv=c.y; bi=q0+1; }
        if (!(nib & 4u) && c.z < bv) { bv=c.z; bi=q0+2; }
        if (!(nib & 8u) && c.w < bv) { bv=c.w; bi=q0+3; }
    }
    s_rv[t]=bv; s_ri[t]=bi;
    __syncthreads();
    for (int s=TCM/2; s>=1; s>>=1) {
        if (t < s) {
            float ov=s_rv[t+s]; int oi=s_ri[t+s];
            if (ov < s_rv[t] || (ov==s_rv[t] && oi < s_ri[t])) { s_rv[t]=ov; s_ri[t]=oi; }
        }
        __syncthreads();
    }
    if (t==0 && s_ri[0] < Q)
        atomicOr(&g_mask[b*Q + s_ri[0]], 1ULL<<g);
}

// =====================================================================
// Kernel C3: output — sel/asn per row; out_mq via packed smem atomicMin.
// =====================================================================
#define TDO 1024
__device__ __forceinline__ unsigned ordf(float v) {
    unsigned u = __float_as_uint(v);
    return (u & 0x80000000u) ? ~u : (u | 0x80000000u);
}
__global__ void __launch_bounds__(TDO)
output_kernel(char* __restrict__ out_bytes, int layoutB)
{
    int b = blockIdx.x, t = threadIdx.x;
    const float* cost = g_cost + (long long)b*G*Q;
    const unsigned* bmp = g_bmp + b*NWORD;
    float penT = (g_nun[b] > 0) ? 100000.0f : 0.0f;

    __shared__ unsigned long long s_pk[G];
    if (t < G) s_pk[t] = 0xFFFFFFFFFFFFFFFFULL;
    __syncthreads();

    unsigned char* out_sel8 = (unsigned char*)out_bytes;
    int*   out_asnI = (int*)(out_bytes + (size_t)BB*Q);
    int*   out_mqI  = (int*)(out_bytes + (size_t)BB*Q + (size_t)4*BB*Q);
    float* outF     = (float*)out_bytes;

    for (int q=t; q<Q; q+=TDO) {
        unsigned long long m = g_mask[b*Q+q];
        if (layoutB) {
            out_sel8[b*Q+q] = m ? 1 : 0;
            out_asnI[b*Q+q] = m ? (__ffsll((long long)m)-1) : 0;
        } else {
            outF[b*Q+q]        = m ? 1.0f : 0.0f;
            outF[BB*Q + b*Q+q] = m ? (float)(__ffsll((long long)m)-1) : 0.0f;
        }
        if (m) {
            float pen = ((bmp[q>>5] >> (q&31)) & 1u) ? penT : 0.0f;
            unsigned long long mm = m;
            while (mm) {
                int g = __ffsll((long long)mm)-1; mm &= mm-1;
                float v = cost[(long long)g*Q + q] + pen;
                unsigned long long pk = ((unsigned long long)ordf(v) << 32) | (unsigned)q;
                atomicMin(&s_pk[g], pk);
            }
        }
    }
    __syncthreads();
    if (t < G) {
        int qmin = (int)(s_pk[t] & 0xFFFFFFFFULL);
        if (layoutB) out_mqI[b*G+t] = qmin;
        else         outF[2*BB*Q + b*G+t] = (float)qmin;
    }
}

// =====================================================================
extern "C" void kernel_launch(void* const* d_in, const int* in_sizes, int n_in,
                              void* d_out, int out_size)
{
    const float* logits = 0; const float* boxes = 0;
    const int*   labels = 0; const float* gtb   = 0;
    for (int i = 0; i < n_in; i++) {
        switch (in_sizes[i]) {
            case BB*Q*CC: logits = (const float*)d_in[i]; break;
            case BB*Q*4:  boxes  = (const float*)d_in[i]; break;
            case BB*G:    labels = (const int*)  d_in[i]; break;
            case BB*G*4:  gtb    = (const float*)d_in[i]; break;
        }
    }

    int layoutB = (out_size == BB*Q + 4*BB*Q + 4*BB*G) ? 1 : 0;

    dim3 gA((Q + QPB - 1)/QPB, BB);
    build_cost_kernel<<<gA, TBA>>>(logits, boxes, labels, gtb);
    select_kernel<<<BB*G, TKB>>>(boxes, gtb);
    prep_kernel<<<BB, TDP>>>();
    colmin_kernel<<<BB*G, TCM>>>();
    output_kernel<<<BB, TDO>>>((char*)d_out, layoutB);
}

// round 11
// speedup vs baseline: 2.0345x; 1.0495x over previous
#include <cuda_runtime.h>
#include <math.h>

#define BB 16
#define Q  8400
#define CC 80
#define G  64
#define RADIUS (2.5f/32.0f)
#define NWORD ((Q+31)/32)
#define Q4 (Q/4)

// ---- scratch (static device globals; no runtime allocation) ----
__device__ float              g_cost[(long long)BB*G*Q];   // [b][g][q]
__device__ unsigned long long g_mask[BB*Q];                // per-anchor GT bitmask
__device__ int                g_rowarg[BB*Q];              // argmin_g cost0[q][g]
__device__ unsigned           g_bmp [BB*NWORD];            // prologue-matched bitmap
__device__ int                g_cnt [BB*G];                // per-column match count

// =====================================================================
// Kernel A: warp-per-anchor cost build; fast transcendentals.
// Also zeroes g_cnt (block x==0) for the downstream prep.
// =====================================================================
#define TBA 512
#define QPB 16
__global__ void __launch_bounds__(TBA)
build_cost_kernel(const float* __restrict__ logits,
                  const float* __restrict__ boxes,
                  const int*   __restrict__ labels,
                  const float* __restrict__ gtboxes)
{
    int b = blockIdx.y;
    int qbase = blockIdx.x * QPB;
    int t = threadIdx.x;
    int w = t >> 5, l = t & 31;

    if (blockIdx.x == 0 && t < G) g_cnt[b*G + t] = 0;

    __shared__ float4 s_gx4[G];
    __shared__ float  s_cx[G], s_cy[G], s_area[G];
    __shared__ int    s_lab[G];
    __shared__ float  s_cost[G][QPB+1];

    if (t < G) {
        float4 gb = ((const float4*)gtboxes)[b*G + t];
        s_cx[t]=gb.x; s_cy[t]=gb.y;
        float x0=gb.x-0.5f*gb.z, y0=gb.y-0.5f*gb.w;
        float x1=gb.x+0.5f*gb.z, y1=gb.y+0.5f*gb.w;
        s_gx4[t] = make_float4(x0,y0,x1,y1);
        s_area[t]=(x1-x0)*(y1-y0);
        s_lab[t]=labels[b*G+t];
    }
    __syncthreads();

    int q = qbase + w;
    if (q < Q) {
        float4 pb = ((const float4*)boxes)[b*Q + q];
        float ax = pb.x, ay = pb.y;
        float bx0 = pb.x-0.5f*pb.z, by0 = pb.y-0.5f*pb.w;
        float bx1 = pb.x+0.5f*pb.z, by1 = pb.y+0.5f*pb.w;
        float areaA = (bx1-bx0)*(by1-by0);
        const float* lrow = logits + ((long long)b*Q + q)*CC;

        float costv[2];
        bool  anyflag = false;
        bool  iibcv[2];

        #pragma unroll
        for (int h=0; h<2; h++) {
            int g = l + h*32;
            float4 gx = s_gx4[g];
            bool ib = (ax>gx.x) && (ax<gx.z) && (ay>gx.y) && (ay<gx.w);
            bool ic = (ax>s_cx[g]-RADIUS)&&(ax<s_cx[g]+RADIUS)&&
                      (ay>s_cy[g]-RADIUS)&&(ay<s_cy[g]+RADIUS);
            anyflag |= (ib | ic);
            iibcv[h] = ib && ic;
        }
        unsigned ball = __ballot_sync(0xffffffffu, anyflag);
        float fgterm = ball ? 0.0f : 10000.0f;

        #pragma unroll
        for (int h=0; h<2; h++) {
            int g = l + h*32;
            float x = __ldg(lrow + s_lab[g]);
            float p = __fdividef(1.0f, 1.0f + __expf(-x));
            float neg = 0.75f * p*p * (-__logf(1.0f - p + 1e-8f));
            float pos = 0.25f * (1.0f-p)*(1.0f-p) * (-__logf(p + 1e-8f));
            float cls = pos - neg;

            float4 gx = s_gx4[g];
            float ltx=fmaxf(bx0,gx.x), lty=fmaxf(by0,gx.y);
            float rbx=fminf(bx1,gx.z), rby=fminf(by1,gx.w);
            float iw=fmaxf(rbx-ltx,0.0f), ih=fmaxf(rby-lty,0.0f);
            float inter = iw*ih;
            float uni   = areaA + s_area[g] - inter;
            float iou   = __fdividef(inter, uni);
            float ex0=fminf(bx0,gx.x), ey0=fminf(by0,gx.y);
            float ex1=fmaxf(bx1,gx.z), ey1=fmaxf(by1,gx.w);
            float encl = fmaxf(ex1-ex0,0.0f)*fmaxf(ey1-ey0,0.0f);
            float giou = iou - __fdividef(encl - uni, encl);

            costv[h] = cls - 3.0f*giou + (iibcv[h] ? 0.0f : 100.0f) + fgterm;
            s_cost[g][w] = costv[h];
        }

        float bv; int bg;
        if (costv[1] < costv[0]) { bv = costv[1]; bg = l+32; }
        else                     { bv = costv[0]; bg = l;    }
        #pragma unroll
        for (int off=16; off; off>>=1) {
            float ov = __shfl_down_sync(0xffffffffu, bv, off);
            int   og = __shfl_down_sync(0xffffffffu, bg, off);
            if (ov < bv || (ov==bv && og < bg)) { bv=ov; bg=og; }
        }
        if (l==0) {
            g_rowarg[b*Q+q] = bg;
            g_mask  [b*Q+q] = 0ULL;
        }
    }
    __syncthreads();

    int r0 = t >> 4, j = t & 15;
    int qq = qbase + j;
    if (qq < Q) {
        float* p = g_cost + ((long long)b*G + r0)*Q + qq;
        #pragma unroll
        for (int r = r0; r < G; r += 32) {
            *p = s_cost[r][j];
            p += (size_t)32*Q;
        }
    }
}

// =====================================================================
// Kernel B: per (b,g) column select; x4-vectorized scan; register-
// resident lists and merges.
// =====================================================================
#define TKB 256
__global__ void __launch_bounds__(TKB)
select_kernel(const float* __restrict__ boxes,
              const float* __restrict__ gtboxes)
{
    int b = blockIdx.x >> 6, g = blockIdx.x & 63;
    const float4* cost4 = (const float4*)(g_cost + ((long long)b*G+g)*Q);
    const float4* abox = (const float4*)boxes + (long long)b*Q;
    int t = threadIdx.x;

    float4 gb = __ldg(&((const float4*)gtboxes)[b*G+g]);
    float gx0=gb.x-0.5f*gb.z, gy0=gb.y-0.5f*gb.w;
    float gx1=gb.x+0.5f*gb.z, gy1=gb.y+0.5f*gb.w;
    float areaG=(gx1-gx0)*(gy1-gy0);

    __shared__ float s_iv[TKB*10];
    __shared__ float s_pv[TKB*10];
    __shared__ int   s_pi[TKB*10];

    float itop[10];
    float pv[10]; int pi[10];
    #pragma unroll
    for (int i=0;i<10;i++) { itop[i]=-INFINITY; pv[i]=INFINITY; pi[i]=0x7FFFFFFF; }

    // ---- x4 scan ----
    for (int i=t; i<Q4; i+=TKB) {
        float4 cv4 = __ldg(cost4 + i);
        int q0 = i*4;
        #pragma unroll
        for (int j=0; j<4; j++) {
            float4 pb = __ldg(abox + q0 + j);
            float bx0 = pb.x-0.5f*pb.z, by0 = pb.y-0.5f*pb.w;
            float bx1 = pb.x+0.5f*pb.z, by1 = pb.y+0.5f*pb.w;
            float areaA = (bx1-bx0)*(by1-by0);
            float ltx=fmaxf(bx0,gx0), lty=fmaxf(by0,gy0);
            float rbx=fminf(bx1,gx1), rby=fminf(by1,gy1);
            float iw=fmaxf(rbx-ltx,0.0f), ih=fmaxf(rby-lty,0.0f);
            float inter = iw*ih;
            float uni   = areaA + areaG - inter;
            float iou   = __fdividef(inter, uni);

            if (iou > itop[9]) {
                float nv = iou;
                #pragma unroll
                for (int k=0;k<10;k++) {
                    float cur = itop[k];
                    bool take = nv > cur;
                    itop[k] = take ? nv : cur;
                    nv      = take ? cur : nv;
                }
            }
            float v = (j==0)?cv4.x:(j==1)?cv4.y:(j==2)?cv4.z:cv4.w;
            if (v < pv[9]) {
                float nv = v; int ni = q0 + j;
                #pragma unroll
                for (int k=0;k<10;k++) {
                    float cvk = pv[k]; int cik = pi[k];
                    bool take = (nv < cvk) || (nv == cvk && ni < cik);
                    pv[k] = take ? nv : cvk;  pi[k] = take ? ni : cik;
                    nv    = take ? cvk : nv;  ni    = take ? cik : ni;
                }
            }
        }
    }

    #pragma unroll
    for (int i=0;i<10;i++) {
        s_iv[t*10+i]=itop[i]; s_pv[t*10+i]=pv[i]; s_pi[t*10+i]=pi[i];
    }
    __syncthreads();

    for (int s=TKB/2; s>=1; s>>=1) {
        if (t < s) {
            int o = (t+s)*10;
            float ci[10];
            #pragma unroll
            for (int i=0;i<10;i++) ci[i] = fmaxf(itop[i], s_iv[o+9-i]);
            #pragma unroll
            for (int r=0;r<10;r++) {
                #pragma unroll
                for (int i=0;i<9;i++) {
                    if (((i^r)&1)==0) {
                        float a=ci[i], c2=ci[i+1];
                        ci[i]=fmaxf(a,c2); ci[i+1]=fminf(a,c2);
                    }
                }
            }
            #pragma unroll
            for (int i=0;i<10;i++) itop[i]=ci[i];

            float cv[10]; int cx[10];
            #pragma unroll
            for (int i=0;i<10;i++) {
                float ov2 = s_pv[o+9-i]; int oi2 = s_pi[o+9-i];
                bool mineWins = (pv[i] < ov2) || (pv[i]==ov2 && pi[i] < oi2);
                cv[i] = mineWins ? pv[i] : ov2;
                cx[i] = mineWins ? pi[i] : oi2;
            }
            #pragma unroll
            for (int r=0;r<10;r++) {
                #pragma unroll
                for (int i=0;i<9;i++) {
                    if (((i^r)&1)==0) {
                        float a=cv[i], c2=cv[i+1];
                        int   ai=cx[i], ci2=cx[i+1];
                        bool sw = (a > c2) || (a==c2 && ai > ci2);
                        cv[i]   = sw ? c2 : a;   cv[i+1] = sw ? a  : c2;
                        cx[i]   = sw ? ci2: ai;  cx[i+1] = sw ? ai : ci2;
                    }
                }
            }
            #pragma unroll
            for (int i=0;i<10;i++) { pv[i]=cv[i]; pi[i]=cx[i]; }

            #pragma unroll
            for (int i=0;i<10;i++) {
                s_iv[t*10+i]=itop[i]; s_pv[t*10+i]=pv[i]; s_pi[t*10+i]=pi[i];
            }
        }
        __syncthreads();
    }

    if (t==0) {
        float ssum = 0.0f;
        #pragma unroll
        for (int i=0;i<10;i++) ssum += itop[i];
        int k = (int)ssum;
        if (k < 1) k = 1;
        if (k > 10) k = 10;
        for (int j=0; j<k; j++)
            atomicOr(&g_mask[b*Q + pi[j]], 1ULL<<g);
    }
}

// =====================================================================
// Kernel C1: prep — grid (BB,8) segment blocks; warp-per-word dedup +
// ballot bitmap; counts via global atomics (few hundred per image).
// =====================================================================
#define SEGN 8
#define SEGW ((NWORD + SEGN - 1)/SEGN)   // 33
#define TDP 1024
__global__ void __launch_bounds__(TDP)
prep_kernel()
{
    int b = blockIdx.x, seg = blockIdx.y, t = threadIdx.x;
    int wid = t >> 5, lane = t & 31;
    int w0 = seg*SEGW, w1 = min(w0 + SEGW, NWORD);

    for (int w = w0 + wid; w < w1; w += TDP/32) {
        int q = w*32 + lane;
        bool matched = false;
        if (q < Q) {
            unsigned long long m = g_mask[b*Q+q];
            if (__popcll(m) > 1) {
                m = 1ULL << g_rowarg[b*Q+q];
                g_mask[b*Q+q] = m;
            }
            if (m) {
                matched = true;
                unsigned long long mm = m;
                while (mm) { int g = __ffsll((long long)mm)-1; atomicAdd(&g_cnt[b*G+g],1); mm &= mm-1; }
            }
        }
        unsigned word = __ballot_sync(0xffffffffu, matched);
        if (lane == 0) g_bmp[b*NWORD + w] = word;
    }
}

// =====================================================================
// Kernel C2: colmin — one block per (b,g); unmatched columns only.
// =====================================================================
#define TCM 256
__global__ void __launch_bounds__(TCM)
colmin_kernel()
{
    int b = blockIdx.x >> 6, g = blockIdx.x & 63;
    if (g_cnt[b*G+g] != 0) return;
    int t = threadIdx.x;
    const float4* cg4 = (const float4*)(g_cost + ((long long)b*G+g)*Q);
    const unsigned* bmp = g_bmp + b*NWORD;

    __shared__ float s_rv[TCM];
    __shared__ int   s_ri[TCM];

    float bv = INFINITY; int bi = Q;
    for (int i=t; i<Q4; i+=TCM) {
        unsigned nib = (bmp[i>>3] >> ((i&7)*4)) & 0xFu;
        float4 c = __ldg(cg4 + i);
        int q0 = i*4;
        if (!(nib & 1u) && c.x < bv) { bv=c.x; bi=q0;   }
        if (!(nib & 2u) && c.y < bv) { bv=c.y; bi=q0+1; }
        if (!(nib & 4u) && c.z < bv) { bv=c.z; bi=q0+2; }
        if (!(nib & 8u) && c.w < bv) { bv=c.w; bi=q0+3; }
    }
    s_rv[t]=bv; s_ri[t]=bi;
    __syncthreads();
    for (int s=TCM/2; s>=1; s>>=1) {
        if (t < s) {
            float ov=s_rv[t+s]; int oi=s_ri[t+s];
            if (ov < s_rv[t] || (ov==s_rv[t] && oi < s_ri[t])) { s_rv[t]=ov; s_ri[t]=oi; }
        }
        __syncthreads();
    }
    if (t==0 && s_ri[0] < Q)
        atomicOr(&g_mask[b*Q + s_ri[0]], 1ULL<<g);
}

// =====================================================================
// Kernel C3: output — sel/asn per row; out_mq via packed smem atomicMin;
// penT derived from g_cnt.
// =====================================================================
#define TDO 1024
__device__ __forceinline__ unsigned ordf(float v) {
    unsigned u = __float_as_uint(v);
    return (u & 0x80000000u) ? ~u : (u | 0x80000000u);
}
__global__ void __launch_bounds__(TDO)
output_kernel(char* __restrict__ out_bytes, int layoutB)
{
    int b = blockIdx.x, t = threadIdx.x;
    const float* cost = g_cost + (long long)b*G*Q;
    const unsigned* bmp = g_bmp + b*NWORD;

    __shared__ unsigned long long s_pk[G];
    __shared__ int s_un;
    if (t < G) s_pk[t] = 0xFFFFFFFFFFFFFFFFULL;
    if (t == 0) s_un = 0;
    __syncthreads();
    if (t < G && g_cnt[b*G+t] == 0) s_un = 1;
    __syncthreads();
    float penT = s_un ? 100000.0f : 0.0f;

    unsigned char* out_sel8 = (unsigned char*)out_bytes;
    int*   out_asnI = (int*)(out_bytes + (size_t)BB*Q);
    int*   out_mqI  = (int*)(out_bytes + (size_t)BB*Q + (size_t)4*BB*Q);
    float* outF     = (float*)out_bytes;

    for (int q=t; q<Q; q+=TDO) {
        unsigned long long m = g_mask[b*Q+q];
        if (layoutB) {
            out_sel8[b*Q+q] = m ? 1 : 0;
            out_asnI[b*Q+q] = m ? (__ffsll((long long)m)-1) : 0;
        } else {
            outF[b*Q+q]        = m ? 1.0f : 0.0f;
            outF[BB*Q + b*Q+q] = m ? (float)(__ffsll((long long)m)-1) : 0.0f;
        }
        if (m) {
            float pen = ((bmp[q>>5] >> (q&31)) & 1u) ? penT : 0.0f;
            unsigned long long mm = m;
            while (mm) {
                int g = __ffsll((long long)mm)-1; mm &= mm-1;
                float v = cost[(long long)g*Q + q] + pen;
                unsigned long long pk = ((unsigned long long)ordf(v) << 32) | (unsigned)q;
                atomicMin(&s_pk[g], pk);
            }
        }
    }
    __syncthreads();
    if (t < G) {
        int qmin = (int)(s_pk[t] & 0xFFFFFFFFULL);
        if (layoutB) out_mqI[b*G+t] = qmin;
        else         outF[2*BB*Q + b*G+t] = (float)qmin;
    }
}

// =====================================================================
extern "C" void kernel_launch(void* const* d_in, const int* in_sizes, int n_in,
                              void* d_out, int out_size)
{
    const float* logits = 0; const float* boxes = 0;
    const int*   labels = 0; const float* gtb   = 0;
    for (int i = 0; i < n_in; i++) {
        switch (in_sizes[i]) {
            case BB*Q*CC: logits = (const float*)d_in[i]; break;
            case BB*Q*4:  boxes  = (const float*)d_in[i]; break;
            case BB*G:    labels = (const int*)  d_in[i]; break;
            case BB*G*4:  gtb    = (const float*)d_in[i]; break;
        }
    }

    int layoutB = (out_size == BB*Q + 4*BB*Q + 4*BB*G) ? 1 : 0;

    dim3 gA((Q + QPB - 1)/QPB, BB);
    build_cost_kernel<<<gA, TBA>>>(logits, boxes, labels, gtb);
    select_kernel<<<BB*G, TKB>>>(boxes, gtb);
    dim3 gP(BB, SEGN);
    prep_kernel<<<gP, TDP>>>();
    colmin_kernel<<<BB*G, TCM>>>();
    output_kernel<<<BB, TDO>>>((char*)d_out, layoutB);
}